// round 13
// baseline (speedup 1.0000x reference)
#include <cuda_runtime.h>
#include <cuda_bf16.h>

// Problem constants
#define BB 8
#define LL 8192
#define DD 512
#define SF 4
#define RR 32                 // rows per chunk
#define CH (LL / RR)          // 256 chunks per batch
#define NCHUNK (BB * CH)      // 2048 total chunks
#define OUT_L (LL / SF)       // 2048
#define D4 (DD / 4)           // 128 float4 lanes
#define OUTG (RR / SF)        // 8 output rows per chunk
#define NSUP 16               // supers per batch
#define SUPC (CH / NSUP)      // 16 chunks per super
#define GRIDN NCHUNK          // 2048 blocks, one chunk each

// Scratch
__device__ float g_part[BB][CH][DD];        // per-chunk aggregates (4 MB)
__device__ float g_sup[BB][NSUP][DD];       // per-super sums (256 KB)
__device__ float g_base[BB][CH][DD];        // per-chunk exclusive bases (4 MB)
__device__ unsigned g_bar;                  // monotonic barrier counter
__device__ unsigned g_done;                 // end-of-kernel cleanup counter

__device__ __forceinline__ unsigned ld_acq_u(const unsigned* p) {
    unsigned v;
    asm volatile("ld.acquire.gpu.u32 %0, [%1];" : "=r"(v) : "l"(p) : "memory");
    return v;
}

// Grid barrier: safe because launch_bounds(128,14) + 14.3KB smem/block give
// 14 blocks/SM capacity; 2048 <= 148*14 = 2072, so all blocks co-resident.
__device__ __forceinline__ void gsync(unsigned target) {
    __syncthreads();
    if (threadIdx.x == 0) {
        __threadfence();                       // release prior writes
        atomicAdd(&g_bar, 1u);
        while (ld_acq_u(&g_bar) < target) __nanosleep(128);
    }
    __syncthreads();
    __threadfence();                           // acquire others' writes
}

__global__ __launch_bounds__(128, 14) void k_all(const float* __restrict__ x,
                                                 float* __restrict__ out) {
    // Partial prefixes for g=0..6 live here across the grid barrier (14,336 B).
    __shared__ float4 s_part[OUTG - 1][D4];

    const int tid = threadIdx.x;
    const int d4 = tid;
    const int t = blockIdx.x;          // chunk id == block id
    const int b = t >> 8;
    const int c = t & (CH - 1);

    // ── Phase A: local chunk scan; partials -> smem, aggregate -> g_part ──
    const float4* xp = reinterpret_cast<const float4*>(
        x + ((size_t)b * LL + (size_t)c * RR) * DD) + d4;

    float4 acc = make_float4(0.f, 0.f, 0.f, 0.f);
#pragma unroll
    for (int g = 0; g < OUTG; ++g) {
        float4 v0 = __ldcs(xp + (size_t)(g * SF + 0) * D4);
        float4 v1 = __ldcs(xp + (size_t)(g * SF + 1) * D4);
        float4 v2 = __ldcs(xp + (size_t)(g * SF + 2) * D4);
        float4 v3 = __ldcs(xp + (size_t)(g * SF + 3) * D4);
        acc.x += (v0.x + v1.x) + (v2.x + v3.x);
        acc.y += (v0.y + v1.y) + (v2.y + v3.y);
        acc.z += (v0.z + v1.z) + (v2.z + v3.z);
        acc.w += (v0.w + v1.w) + (v2.w + v3.w);
        if (g < OUTG - 1) s_part[g][d4] = acc;  // g=7 partial == acc, stays in regs
    }
    reinterpret_cast<float4*>(g_part[b][c])[d4] = acc;

    gsync(GRIDN);

    // ── Phase B1: super sums (blocks 0..127) ──
    if (t < BB * NSUP) {
        const int sb = t >> 4;
        const int s = t & (NSUP - 1);
        float4 sum = make_float4(0.f, 0.f, 0.f, 0.f);
#pragma unroll
        for (int k = 0; k < SUPC; ++k) {
            float4 v = reinterpret_cast<const float4*>(g_part[sb][s * SUPC + k])[d4];
            sum.x += v.x; sum.y += v.y; sum.z += v.z; sum.w += v.w;
        }
        reinterpret_cast<float4*>(g_sup[sb][s])[d4] = sum;
    }

    gsync(2u * GRIDN);

    // ── Phase B2: per-chunk exclusive bases (blocks 0..127, one super each) ──
    if (t < BB * NSUP) {
        const int sb = t >> 4;
        const int s = t & (NSUP - 1);
        float4 run = make_float4(0.f, 0.f, 0.f, 0.f);
        for (int j = 0; j < s; ++j) {
            float4 v = reinterpret_cast<const float4*>(g_sup[sb][j])[d4];
            run.x += v.x; run.y += v.y; run.z += v.z; run.w += v.w;
        }
#pragma unroll
        for (int k = 0; k < SUPC; ++k) {
            const int cc = s * SUPC + k;
            reinterpret_cast<float4*>(g_base[sb][cc])[d4] = run;
            float4 v = reinterpret_cast<const float4*>(g_part[sb][cc])[d4];
            run.x += v.x; run.y += v.y; run.z += v.z; run.w += v.w;
        }
    }

    gsync(3u * GRIDN);

    // ── Phase C: single final write: out = (partial + base) / count ──
    const float4 base = reinterpret_cast<const float4*>(g_base[b][c])[d4];
    float4* op = reinterpret_cast<float4*>(
        out + ((size_t)b * OUT_L + (size_t)c * OUTG) * DD) + d4;
#pragma unroll
    for (int g = 0; g < OUTG; ++g) {
        const float inv = 1.0f / (float)(c * RR + g * SF + SF);
        float4 p = (g < OUTG - 1) ? s_part[g][d4] : acc;   // acc survived in regs
        float4 o;
        o.x = (p.x + base.x) * inv;
        o.y = (p.y + base.y) * inv;
        o.z = (p.z + base.z) * inv;
        o.w = (p.w + base.w) * inv;
        op[(size_t)g * D4] = o;
    }

    // ── Cleanup: last block resets counters for the next graph replay ──
    __syncthreads();
    if (tid == 0) {
        __threadfence();
        unsigned v = atomicAdd(&g_done, 1u);
        if (v == GRIDN - 1) {
            g_bar = 0u; g_done = 0u;
            __threadfence();
        }
    }
}

extern "C" void kernel_launch(void* const* d_in, const int* in_sizes, int n_in,
                              void* d_out, int out_size) {
    const float* x = (const float*)d_in[0];
    float* out = (float*)d_out;

    k_all<<<GRIDN, 128>>>(x, out);
}

// round 14
// speedup vs baseline: 1.2809x; 1.2809x over previous
#include <cuda_runtime.h>
#include <cuda_bf16.h>

// Problem constants
#define BB 8
#define LL 8192
#define DD 512
#define SF 4
#define RR 32                 // rows per chunk
#define CH (LL / RR)          // 256 chunks per batch
#define NCHUNK (BB * CH)      // 2048 total chunks
#define OUT_L (LL / SF)       // 2048
#define D4 (DD / 4)           // 128 float4 lanes
#define OUTG (RR / SF)        // 8 output rows per chunk
#define NSUP 16               // supers per batch
#define SUPC (CH / NSUP)      // 16 chunks per super
#define GRIDN 1024            // R9 geometry: all co-resident at 8 blocks/SM
#define CPB (NCHUNK / GRIDN)  // 2 chunks per block (uniform)
#define SMEMG 6               // partials g=0..5 in smem; g=6,7 in regs

// Scratch
__device__ float g_part[BB][CH][DD];        // per-chunk aggregates (4 MB)
__device__ float g_sup[BB][NSUP][DD];       // per-super sums (256 KB)
__device__ unsigned g_bar;                  // monotonic barrier counter
__device__ unsigned g_done;                 // end-of-kernel cleanup counter

__device__ __forceinline__ unsigned ld_acq_u(const unsigned* p) {
    unsigned v;
    asm volatile("ld.acquire.gpu.u32 %0, [%1];" : "=r"(v) : "l"(p) : "memory");
    return v;
}

// Grid barrier: safe because launch_bounds(128,8) + 24.6KB smem/block give
// 8 blocks/SM (200KB smem, 32 warps); 1024 <= 148*8 = 1184 co-resident.
__device__ __forceinline__ void gsync(unsigned target) {
    __syncthreads();
    if (threadIdx.x == 0) {
        __threadfence();                       // release prior writes
        atomicAdd(&g_bar, 1u);
        while (ld_acq_u(&g_bar) < target) __nanosleep(128);
    }
    __syncthreads();
    __threadfence();                           // acquire others' writes
}

__global__ __launch_bounds__(128, 8) void k_all(const float* __restrict__ x,
                                                float* __restrict__ out) {
    // Partial prefixes g=0..5 per chunk survive the barrier here (24,576 B).
    __shared__ float4 s_part[CPB][SMEMG][D4];

    const int tid = threadIdx.x;
    const int d4 = tid;
    const int bid = blockIdx.x;

    float4 keep6[CPB];   // g=6 partial per chunk (regs)
    float4 keep7[CPB];   // g=7 partial == chunk aggregate (regs)

    // ── Phase A: pure-read local scans; partials -> smem/regs, agg -> g_part ──
#pragma unroll
    for (int u = 0; u < CPB; ++u) {
        const int t = bid * CPB + u;
        const int b = t >> 8;
        const int c = t & (CH - 1);
        const float4* xp = reinterpret_cast<const float4*>(
            x + ((size_t)b * LL + (size_t)c * RR) * DD) + d4;

        float4 acc = make_float4(0.f, 0.f, 0.f, 0.f);
#pragma unroll
        for (int g = 0; g < OUTG; ++g) {
            float4 v0 = __ldcs(xp + (size_t)(g * SF + 0) * D4);
            float4 v1 = __ldcs(xp + (size_t)(g * SF + 1) * D4);
            float4 v2 = __ldcs(xp + (size_t)(g * SF + 2) * D4);
            float4 v3 = __ldcs(xp + (size_t)(g * SF + 3) * D4);
            acc.x += (v0.x + v1.x) + (v2.x + v3.x);
            acc.y += (v0.y + v1.y) + (v2.y + v3.y);
            acc.z += (v0.z + v1.z) + (v2.z + v3.z);
            acc.w += (v0.w + v1.w) + (v2.w + v3.w);
            if (g < SMEMG)       s_part[u][g][d4] = acc;
            else if (g == SMEMG) keep6[u] = acc;
        }
        keep7[u] = acc;
        reinterpret_cast<float4*>(g_part[b][c])[d4] = acc;
    }

    gsync(GRIDN);

    // ── Phase B: super sums (blocks 0..127) ──
    if (bid < BB * NSUP) {
        const int b = bid >> 4;
        const int s = bid & (NSUP - 1);
        float4 sum = make_float4(0.f, 0.f, 0.f, 0.f);
#pragma unroll
        for (int k = 0; k < SUPC; ++k) {
            float4 v = reinterpret_cast<const float4*>(g_part[b][s * SUPC + k])[d4];
            sum.x += v.x; sum.y += v.y; sum.z += v.z; sum.w += v.w;
        }
        reinterpret_cast<float4*>(g_sup[b][s])[d4] = sum;
    }

    gsync(2u * GRIDN);

    // ── Phase C: base from hierarchy (L2-hot), single final write of out ──
#pragma unroll
    for (int u = 0; u < CPB; ++u) {
        const int t = bid * CPB + u;
        const int b = t >> 8;
        const int c = t & (CH - 1);
        const int s = c >> 4;
        const int nin = c & (SUPC - 1);

        float4 base = make_float4(0.f, 0.f, 0.f, 0.f);
        for (int j = 0; j < s; ++j) {
            float4 v = reinterpret_cast<const float4*>(g_sup[b][j])[d4];
            base.x += v.x; base.y += v.y; base.z += v.z; base.w += v.w;
        }
        for (int j = 0; j < nin; ++j) {
            float4 v = reinterpret_cast<const float4*>(g_part[b][s * SUPC + j])[d4];
            base.x += v.x; base.y += v.y; base.z += v.z; base.w += v.w;
        }

        float4* op = reinterpret_cast<float4*>(
            out + ((size_t)b * OUT_L + (size_t)c * OUTG) * DD) + d4;
#pragma unroll
        for (int g = 0; g < OUTG; ++g) {
            const float inv = 1.0f / (float)(c * RR + g * SF + SF);
            float4 p = (g < SMEMG) ? s_part[u][g][d4]
                     : (g == SMEMG) ? keep6[u] : keep7[u];
            float4 o;
            o.x = (p.x + base.x) * inv;
            o.y = (p.y + base.y) * inv;
            o.z = (p.z + base.z) * inv;
            o.w = (p.w + base.w) * inv;
            op[(size_t)g * D4] = o;
        }
    }

    // ── Cleanup: last block resets counters for the next graph replay ──
    __syncthreads();
    if (tid == 0) {
        __threadfence();
        unsigned v = atomicAdd(&g_done, 1u);
        if (v == GRIDN - 1) {
            g_bar = 0u; g_done = 0u;
            __threadfence();
        }
    }
}

extern "C" void kernel_launch(void* const* d_in, const int* in_sizes, int n_in,
                              void* d_out, int out_size) {
    const float* x = (const float*)d_in[0];
    float* out = (float*)d_out;

    k_all<<<GRIDN, 128>>>(x, out);
}